// round 1
// baseline (speedup 1.0000x reference)
#include <cuda_runtime.h>

#define T_   256
#define B_   8
#define U_   128
#define DE   512
#define H_   512
#define MENC (T_*B_)        // 2048 rows of enc_proj, row index = t*B + b
#define MDEC (B_*U_)        // 1024 rows of dec_proj, row index = b*U + u
#define MTOT (MENC + MDEC)  // 3072

// Scratch for projections: enc_proj rows [0,2048), dec_proj rows [2048,3072)
__device__ float g_proj[(size_t)MTOT * H_];

// ---------------------------------------------------------------------------
// Fused dual GEMM: rows < 2048 -> enc @ W[:512] + bias ; rows >= 2048 -> dec @ W[512:]
// Classic 64x64 tile, BK=16, 256 threads, 4x4 per thread.
// ---------------------------------------------------------------------------
__global__ __launch_bounds__(256) void gemm_kernel(
    const float* __restrict__ enc,   // (2048, 512)
    const float* __restrict__ dec,   // (1024, 512)
    const float* __restrict__ W,     // (1024, 512)
    const float* __restrict__ bias)  // (512)
{
    __shared__ float As[16][64];
    __shared__ float Bs[16][64];

    const int tidx = threadIdx.x;
    const int tx = tidx & 15;    // n-dir (x4)
    const int ty = tidx >> 4;    // m-dir (x4)

    const int mBlock = blockIdx.y * 64;
    const int nBlock = blockIdx.x * 64;
    const bool isEnc = (mBlock < MENC);

    const float* A = isEnc ? (enc + (size_t)mBlock * DE)
                           : (dec + (size_t)(mBlock - MENC) * DE);
    const float* Bm = W + (isEnc ? 0 : (size_t)DE * H_);

    // A-tile loader: thread -> A[ar][ak..ak+3]
    const int ar = tidx >> 2;            // 0..63
    const int ak = (tidx & 3) * 4;       // 0,4,8,12
    // B-tile loader: thread -> B[br][bc..bc+3]
    const int br = tidx >> 4;            // 0..15
    const int bc = (tidx & 15) * 4;      // 0..60

    float acc[4][4];
#pragma unroll
    for (int i = 0; i < 4; i++)
#pragma unroll
        for (int j = 0; j < 4; j++) acc[i][j] = 0.0f;

    for (int k0 = 0; k0 < DE; k0 += 16) {
        float4 a4 = *(const float4*)(A + (size_t)ar * DE + k0 + ak);
        As[ak + 0][ar] = a4.x;
        As[ak + 1][ar] = a4.y;
        As[ak + 2][ar] = a4.z;
        As[ak + 3][ar] = a4.w;
        float4 b4 = *(const float4*)(Bm + (size_t)(k0 + br) * H_ + nBlock + bc);
        *(float4*)&Bs[br][bc] = b4;
        __syncthreads();

#pragma unroll
        for (int k = 0; k < 16; k++) {
            float4 av = *(float4*)&As[k][ty * 4];
            float4 bv = *(float4*)&Bs[k][tx * 4];
            acc[0][0] += av.x * bv.x; acc[0][1] += av.x * bv.y; acc[0][2] += av.x * bv.z; acc[0][3] += av.x * bv.w;
            acc[1][0] += av.y * bv.x; acc[1][1] += av.y * bv.y; acc[1][2] += av.y * bv.z; acc[1][3] += av.y * bv.w;
            acc[2][0] += av.z * bv.x; acc[2][1] += av.z * bv.y; acc[2][2] += av.z * bv.z; acc[2][3] += av.z * bv.w;
            acc[3][0] += av.w * bv.x; acc[3][1] += av.w * bv.y; acc[3][2] += av.w * bv.z; acc[3][3] += av.w * bv.w;
        }
        __syncthreads();
    }

    float4 bv4 = make_float4(0.f, 0.f, 0.f, 0.f);
    if (isEnc) bv4 = *(const float4*)(bias + nBlock + tx * 4);
#pragma unroll
    for (int i = 0; i < 4; i++) {
        int row = mBlock + ty * 4 + i;
        float4 r = make_float4(acc[i][0] + bv4.x, acc[i][1] + bv4.y,
                               acc[i][2] + bv4.z, acc[i][3] + bv4.w);
        *(float4*)&g_proj[(size_t)row * H_ + nBlock + tx * 4] = r;
    }
}

// ---------------------------------------------------------------------------
// Broadcast + tanh + write: out[b,t,u,h] = tanh(encP[t,b,h] + decP[b,u,h])
// One block per (t,b); 512 threads: 4 u-groups x 128 lanes (float4 over H).
// ---------------------------------------------------------------------------
__device__ __forceinline__ float fast_tanh(float x) {
    // tanh(x) = 1 - 2/(exp(2x)+1); MUFU.EX2 + MUFU.RCP path, ~1e-6 error.
    float p = __expf(x + x);
    return 1.0f - __fdividef(2.0f, p + 1.0f);
}

__global__ __launch_bounds__(512) void joint_kernel(float* __restrict__ out) {
    const int t = blockIdx.x;
    const int b = blockIdx.y;
    const int lane = threadIdx.x & 127;   // h/4 position
    const int grp  = threadIdx.x >> 7;    // 0..3 (u phase)

    const float4* e4 = (const float4*)(g_proj + (size_t)(t * B_ + b) * H_);
    const float4  e  = e4[lane];

    const float4* d4 = (const float4*)(g_proj + (size_t)MENC * H_ + (size_t)b * U_ * H_);
    float4* o4 = (float4*)out + (size_t)(b * T_ + t) * U_ * (H_ / 4);

#pragma unroll 4
    for (int i = 0; i < U_ / 4; i++) {
        const int u = grp + 4 * i;
        float4 d = d4[(size_t)u * (H_ / 4) + lane];
        float4 r;
        r.x = fast_tanh(e.x + d.x);
        r.y = fast_tanh(e.y + d.y);
        r.z = fast_tanh(e.z + d.z);
        r.w = fast_tanh(e.w + d.w);
        o4[(size_t)u * (H_ / 4) + lane] = r;
    }
}

// ---------------------------------------------------------------------------
// fake_src_lengths[b] = ceil(sum(mask[b,:] != padding_idx) / DOWNSAMPLE), DOWNSAMPLE=1
// ---------------------------------------------------------------------------
__global__ void lengths_kernel(const unsigned char* __restrict__ mask,
                               const int* __restrict__ pidx_p,
                               float* __restrict__ out_len) {
    const int b = blockIdx.x;
    const int pidx = pidx_p[0];
    __shared__ int cnt;
    if (threadIdx.x == 0) cnt = 0;
    __syncthreads();
    int tok = (int)mask[b * T_ + threadIdx.x];
    int c = (tok != pidx) ? 1 : 0;
    // warp reduce then atomic
    for (int off = 16; off > 0; off >>= 1)
        c += __shfl_down_sync(0xFFFFFFFFu, c, off);
    if ((threadIdx.x & 31) == 0) atomicAdd(&cnt, c);
    __syncthreads();
    if (threadIdx.x == 0) out_len[b] = (float)cnt;
}

extern "C" void kernel_launch(void* const* d_in, const int* in_sizes, int n_in,
                              void* d_out, int out_size) {
    const float*         enc  = (const float*)d_in[0];          // (T,B,De) = rows t*B+b
    const float*         dec  = (const float*)d_in[1];          // (B,U,Dd) = rows b*U+u
    const unsigned char* mask = (const unsigned char*)d_in[2];  // (B,T) bool
    const float*         W    = (const float*)d_in[3];          // (1024, 512)
    const float*         bias = (const float*)d_in[4];          // (512)
    const int*           pidx = (const int*)d_in[5];            // scalar
    float* out = (float*)d_out;

    dim3 gGrid(H_ / 64, MTOT / 64);   // (8, 48)
    gemm_kernel<<<gGrid, 256>>>(enc, dec, W, bias);

    dim3 jGrid(T_, B_);               // (256, 8)
    joint_kernel<<<jGrid, 512>>>(out);

    const long long hsize = (long long)B_ * T_ * U_ * H_;  // 134217728
    if ((long long)out_size > hsize) {
        lengths_kernel<<<B_, T_>>>(mask, pidx, out + hsize);
    }
    (void)in_sizes; (void)n_in;
}